// round 8
// baseline (speedup 1.0000x reference)
#include <cuda_runtime.h>
#include <cstdint>
#include <math.h>

#define TOKENS 32768
#define NEXP   64
#define KDIM   2048
#define KC     64              // floats per K-chunk (4 k16 steps)
#define NCH    (KDIM / KC)     // 32 chunks
#define TILE_M 128
#define TPB    256
#define NKB16  (KDIM / 16)     // 128 k16 blocks

// W pre-split, fragment-ready bf16: [kb16(128)][nf(8)][lane(32)] = {bh0,bh1,bm0,bm1}
__device__ uint4 g_wperm[NKB16 * 8 * 32];   // 512 KB

static __device__ __forceinline__ uint32_t bfpack(float hi, float lo) {
    uint32_t d;
    asm("cvt.rn.bf16x2.f32 %0, %1, %2;" : "=r"(d) : "f"(hi), "f"(lo));
    return d;
}
static __device__ __forceinline__ float bflo(uint32_t p) { return __uint_as_float(p << 16); }
static __device__ __forceinline__ float bfhi(uint32_t p) { return __uint_as_float(p & 0xFFFF0000u); }

static __device__ __forceinline__ void split_pair(float a, float b, uint32_t& h, uint32_t& m) {
    h = bfpack(b, a);                       // lo = a, hi = b
    m = bfpack(b - bfhi(h), a - bflo(h));
}

static __device__ __forceinline__ void mma16(float* d, const uint32_t* a,
                                             uint32_t b0, uint32_t b1) {
    asm volatile(
        "mma.sync.aligned.m16n8k16.row.col.f32.bf16.bf16.f32 "
        "{%0,%1,%2,%3}, {%4,%5,%6,%7}, {%8,%9}, {%0,%1,%2,%3};"
        : "+f"(d[0]), "+f"(d[1]), "+f"(d[2]), "+f"(d[3])
        : "r"(a[0]), "r"(a[1]), "r"(a[2]), "r"(a[3]), "r"(b0), "r"(b1));
}
static __device__ __forceinline__ void merge2(float& v1, int& i1, float& v2, int& i2, int off) {
    float ov1 = __shfl_xor_sync(0xffffffffu, v1, off);
    int   oi1 = __shfl_xor_sync(0xffffffffu, i1, off);
    float ov2 = __shfl_xor_sync(0xffffffffu, v2, off);
    int   oi2 = __shfl_xor_sync(0xffffffffu, i2, off);
    bool mine = (v1 > ov1) || (v1 == ov1 && i1 < oi1);
    float l1v = mine ? ov1 : v1;  int l1i = mine ? oi1 : i1;
    float s2v = mine ? v2  : ov2; int s2i = mine ? i2  : oi2;
    v1 = mine ? v1 : ov1;  i1 = mine ? i1 : oi1;
    bool sec = (s2v > l1v) || (s2v == l1v && s2i < l1i);
    v2 = sec ? s2v : l1v;  i2 = sec ? s2i : l1i;
}

static __device__ __forceinline__ uint32_t s2u(const void* p) {
    uint32_t a;
    asm("{ .reg .u64 t; cvta.to.shared.u64 t, %1; cvt.u32.u64 %0, t; }" : "=r"(a) : "l"(p));
    return a;
}
static __device__ __forceinline__ void cp16(uint32_t dst, const void* src) {
    asm volatile("cp.async.ca.shared.global [%0], [%1], 16;"
                 :: "r"(dst), "l"(src) : "memory");
}

// ---- prep: split W into bf16 fragment-ready layout (once per launch) ----
extern "C" __global__ void __launch_bounds__(256)
prep_w(const float* __restrict__ W)
{
    int idx  = blockIdx.x * 256 + threadIdx.x;  // 0..32767
    int lane = idx & 31;
    int nf   = (idx >> 5) & 7;
    int kb   = idx >> 8;                        // k16 block 0..127
    int g = lane >> 2, t = lane & 3;
    const float* wr = W + (size_t)(nf * 8 + g) * KDIM + kb * 16;
    uint4 r;
    split_pair(wr[2 * t],     wr[2 * t + 1], r.x, r.z);   // b0 (k = 2t, 2t+1)
    split_pair(wr[2 * t + 8], wr[2 * t + 9], r.y, r.w);   // b1 (k = 2t+8, 2t+9)
    g_wperm[idx] = r;
}

// SMEM per stage (uint4 units): aH[1024] | aM[1024] | B[1024]  -> 3072 uint4 = 48KB
#define STAGE_U4  3072
#define SMEM_BYTES (2 * STAGE_U4 * 16)   // 98304

extern "C" __global__ void __launch_bounds__(TPB, 2)
router_bf16(const float* __restrict__ X, float* __restrict__ out)
{
    extern __shared__ uint4 sm4[];
    const int tid  = threadIdx.x;
    const int wid  = tid >> 5;
    const int lane = tid & 31;
    const int g    = lane >> 2;
    const int t    = lane & 3;
    const int blockM = blockIdx.x * TILE_M;

    if (wid >= 4) {
        // ------------- producers: warps 4..7 -------------
        const int p = tid - 128;   // 0..127
        float4 xa[8], xb[8];       // one chunk of A: 64 floats

        #define PLOAD(c)                                                        \
            {                                                                   \
                _Pragma("unroll")                                               \
                for (int j = 0; j < 8; j++) {                                   \
                    int s_idx = p + 128 * j;          /* 0..1023 */             \
                    int row = s_idx >> 3, q2 = s_idx & 7;                       \
                    const float* src = X + (size_t)(blockM + row) * KDIM        \
                                         + (size_t)(c) * KC + q2 * 8;           \
                    xa[j] = reinterpret_cast<const float4*>(src)[0];            \
                    xb[j] = reinterpret_cast<const float4*>(src)[1];            \
                }                                                               \
            }
        #define PSTORE(c)                                                       \
            {                                                                   \
                uint4* aH = sm4 + ((c) & 1) * STAGE_U4;                         \
                uint4* aM = aH + 1024;                                          \
                _Pragma("unroll")                                               \
                for (int j = 0; j < 8; j++) {                                   \
                    int s_idx = p + 128 * j;                                    \
                    int row = s_idx >> 3, q2 = s_idx & 7;                       \
                    uint4 H, M;                                                 \
                    split_pair(xa[j].x, xa[j].y, H.x, M.x);                     \
                    split_pair(xa[j].z, xa[j].w, H.y, M.y);                     \
                    split_pair(xb[j].x, xb[j].y, H.z, M.z);                     \
                    split_pair(xb[j].z, xb[j].w, H.w, M.w);                     \
                    int a_idx = q2 * 128 + (row ^ q2);                          \
                    aH[a_idx] = H;                                              \
                    aM[a_idx] = M;                                              \
                }                                                               \
            }
        #define PCOPYB(c)                                                       \
            {                                                                   \
                uint32_t sB = s2u(sm4 + ((c) & 1) * STAGE_U4 + 2048);           \
                _Pragma("unroll")                                               \
                for (int j = 0; j < 8; j++) {                                   \
                    int s_idx = p + 128 * j;                                    \
                    cp16(sB + s_idx * 16, g_wperm + (c) * 1024 + s_idx);        \
                }                                                               \
                asm volatile("cp.async.commit_group;" ::: "memory");            \
            }
        #define PWAIT() asm volatile("cp.async.wait_group 0;" ::: "memory")

        PLOAD(0);
        PCOPYB(0);
        PSTORE(0);
        PLOAD(1);
        PWAIT();
        __syncthreads();

        for (int c = 0; c < NCH; c++) {
            if (c + 1 < NCH) {
                PCOPYB(c + 1);
                PSTORE(c + 1);
                if (c + 2 < NCH) PLOAD(c + 2);
                PWAIT();
            }
            __syncthreads();
        }
        return;
    }

    // ------------- consumers: warps 0..3, tile m32 x n64 -------------
    float acc[2][8][4];
    #pragma unroll
    for (int mf = 0; mf < 2; mf++)
        #pragma unroll
        for (int nf = 0; nf < 8; nf++)
            #pragma unroll
            for (int u = 0; u < 4; u++) acc[mf][nf][u] = 0.0f;

    const int wbase = wid * 32;
    __syncthreads();   // match producer prologue

    for (int c = 0; c < NCH; c++) {
        const int s = c & 1;
        const uint32_t* aH = reinterpret_cast<const uint32_t*>(sm4 + s * STAGE_U4);
        const uint32_t* aM = aH + 4096;
        const uint4*    sB = sm4 + s * STAGE_U4 + 2048;

        #pragma unroll
        for (int kb = 0; kb < 4; kb++) {
            const int q0 = 2 * kb, q1 = 2 * kb + 1;
            uint32_t ah[2][4], am[2][4];
            #pragma unroll
            for (int mf = 0; mf < 2; mf++) {
                const int R0 = wbase + mf * 16 + g;
                const int i0 = (q0 * 128 + (R0 ^ q0)) * 4 + t;
                const int i2 = (q1 * 128 + (R0 ^ q1)) * 4 + t;
                ah[mf][0] = aH[i0];       ah[mf][1] = aH[i0 + 32];
                ah[mf][2] = aH[i2];       ah[mf][3] = aH[i2 + 32];
                am[mf][0] = aM[i0];       am[mf][1] = aM[i0 + 32];
                am[mf][2] = aM[i2];       am[mf][3] = aM[i2 + 32];
            }
            // hoist all 8 B fragments into registers
            uint4 b[8];
            #pragma unroll
            for (int nf = 0; nf < 8; nf++)
                b[nf] = sB[(kb * 8 + nf) * 32 + lane];

            // three passes of 16 independent MMAs each:
            // per-acc order stays HH -> HM -> MH per kb (same summation tree)
            #pragma unroll
            for (int nf = 0; nf < 8; nf++)
                #pragma unroll
                for (int mf = 0; mf < 2; mf++)
                    mma16(acc[mf][nf], ah[mf], b[nf].x, b[nf].y);   // Ah*Bh
            #pragma unroll
            for (int nf = 0; nf < 8; nf++)
                #pragma unroll
                for (int mf = 0; mf < 2; mf++)
                    mma16(acc[mf][nf], ah[mf], b[nf].z, b[nf].w);   // Ah*Bm
            #pragma unroll
            for (int nf = 0; nf < 8; nf++)
                #pragma unroll
                for (int mf = 0; mf < 2; mf++)
                    mma16(acc[mf][nf], am[mf], b[nf].x, b[nf].y);   // Am*Bh
        }
        __syncthreads();
    }

    // ------------- epilogue: logits + stable top-2 + softmax -------------
    float* outIdx = out;
    float* outWgt = out + TOKENS * 2;
    float* outLog = out + TOKENS * 4;

    #pragma unroll
    for (int mf = 0; mf < 2; mf++) {
        #pragma unroll
        for (int h = 0; h < 2; h++) {
            const int row = wbase + mf * 16 + h * 8 + g;
            const int tok = blockM + row;

            float v1 = -INFINITY, v2 = -INFINITY;
            int   i1 = 0, i2 = 0;
            #pragma unroll
            for (int nf = 0; nf < 8; nf++) {
                #pragma unroll
                for (int u = 0; u < 2; u++) {
                    float v  = acc[mf][nf][2 * h + u];
                    int   id = nf * 8 + 2 * t + u;
                    if (v > v1)      { v2 = v1; i2 = i1; v1 = v; i1 = id; }
                    else if (v > v2) { v2 = v;  i2 = id; }
                }
            }
            merge2(v1, i1, v2, i2, 1);
            merge2(v1, i1, v2, i2, 2);

            float* lr = outLog + (size_t)tok * NEXP;
            #pragma unroll
            for (int nf = 0; nf < 8; nf++) {
                float2 o = make_float2(acc[mf][nf][2 * h], acc[mf][nf][2 * h + 1]);
                *reinterpret_cast<float2*>(lr + nf * 8 + 2 * t) = o;
            }

            if (t == 0) {
                float e2  = expf(v2 - v1);          // v1 >= v2 -> stable
                float inv = 1.0f / (1.0f + e2);
                outIdx[tok * 2]     = (float)i1;
                outIdx[tok * 2 + 1] = (float)i2;
                outWgt[tok * 2]     = inv;
                outWgt[tok * 2 + 1] = e2 * inv;
            }
        }
    }
}

extern "C" void kernel_launch(void* const* d_in, const int* in_sizes, int n_in,
                              void* d_out, int out_size)
{
    const float* X = (const float*)d_in[0];   // [32768, 2048] fp32
    const float* W = (const float*)d_in[1];   // [64, 2048] fp32
    float* out = (float*)d_out;

    prep_w<<<128, 256>>>(W);

    cudaFuncSetAttribute(router_bf16,
                         cudaFuncAttributeMaxDynamicSharedMemorySize, SMEM_BYTES);
    router_bf16<<<TOKENS / TILE_M, TPB, SMEM_BYTES>>>(X, out);
}

// round 10
// speedup vs baseline: 1.0039x; 1.0039x over previous
#include <cuda_runtime.h>
#include <cstdint>
#include <math.h>

#define TOKENS 32768
#define NEXP   64
#define KDIM   2048
#define KC     64              // floats per K-chunk (4 k16 steps)
#define NCH    (KDIM / KC)     // 32 chunks
#define TILE_M 128
#define TPB    256
#define TMARG  0.01f           // flip-safety margin (~20 sigma of fp16 logit err)

// W fragment-ready fp16: [kb16(128)][nf(8)][lane(32)] = {b0, b1}
__device__ uint2 g_wb[128 * 8 * 32];        // 256 KB
__device__ unsigned char g_flag[TOKENS];    // 1 = needs exact re-rank

static __device__ __forceinline__ uint32_t fpack(float hi, float lo) {
    uint32_t d;
    asm("cvt.rn.f16x2.f32 %0, %1, %2;" : "=r"(d) : "f"(hi), "f"(lo));
    return d;
}
static __device__ __forceinline__ void mma16(float* d, const uint32_t* a,
                                             uint32_t b0, uint32_t b1) {
    asm volatile(
        "mma.sync.aligned.m16n8k16.row.col.f32.f16.f16.f32 "
        "{%0,%1,%2,%3}, {%4,%5,%6,%7}, {%8,%9}, {%0,%1,%2,%3};"
        : "+f"(d[0]), "+f"(d[1]), "+f"(d[2]), "+f"(d[3])
        : "r"(a[0]), "r"(a[1]), "r"(a[2]), "r"(a[3]), "r"(b0), "r"(b1));
}
static __device__ __forceinline__ uint32_t s2u(const void* p) {
    uint32_t a;
    asm("{ .reg .u64 t; cvta.to.shared.u64 t, %1; cvt.u32.u64 %0, t; }" : "=r"(a) : "l"(p));
    return a;
}
static __device__ __forceinline__ void cp16(uint32_t dst, const void* src) {
    asm volatile("cp.async.ca.shared.global [%0], [%1], 16;"
                 :: "r"(dst), "l"(src) : "memory");
}

// top-2 (indexed) + top-3 value merge across lanes
static __device__ __forceinline__ void merge23(float& v1, int& i1, float& v2, int& i2,
                                               float& v3, int off) {
    float w1 = __shfl_xor_sync(0xffffffffu, v1, off);
    int   j1 = __shfl_xor_sync(0xffffffffu, i1, off);
    float w2 = __shfl_xor_sync(0xffffffffu, v2, off);
    int   j2 = __shfl_xor_sync(0xffffffffu, i2, off);
    float w3 = __shfl_xor_sync(0xffffffffu, v3, off);
    // 3rd-of-6 = max(v3, w3, min(v1,w2), min(v2,w1))
    float z3 = fmaxf(fmaxf(fminf(v1, w2), fminf(v2, w1)), fmaxf(v3, w3));
    bool mine = (v1 > w1) || (v1 == w1 && i1 < j1);
    float l1v = mine ? w1 : v1;  int l1i = mine ? j1 : i1;
    float s2v = mine ? v2 : w2;  int s2i = mine ? i2 : j2;
    float nv1 = mine ? v1 : w1;  int ni1 = mine ? i1 : j1;
    bool sec = (s2v > l1v) || (s2v == l1v && s2i < l1i);
    v1 = nv1;  i1 = ni1;
    v2 = sec ? s2v : l1v;  i2 = sec ? s2i : l1i;
    v3 = z3;
}

// ---- prep: W -> fragment-ready fp16 (once per launch) ----
extern "C" __global__ void __launch_bounds__(256)
prep_w(const float* __restrict__ W)
{
    int idx  = blockIdx.x * 256 + threadIdx.x;  // 0..32767
    int lane = idx & 31;
    int nf   = (idx >> 5) & 7;
    int kb   = idx >> 8;                        // k16 block 0..127
    int g = lane >> 2, t = lane & 3;
    const float* wr = W + (size_t)(nf * 8 + g) * KDIM + kb * 16;
    uint2 r;
    r.x = fpack(wr[2 * t + 1], wr[2 * t]);          // b0: k = 2t, 2t+1
    r.y = fpack(wr[2 * t + 9], wr[2 * t + 8]);      // b1: k = 2t+8, 2t+9
    g_wb[idx] = r;
}

// SMEM per stage (uint4): aH[1024] (16KB) | B[512] (8KB) = 1536 u4 = 24KB
#define STAGE_U4  1536
#define SMEM_BYTES (2 * STAGE_U4 * 16)   // 49152

extern "C" __global__ void __launch_bounds__(TPB, 2)
router_f16(const float* __restrict__ X, float* __restrict__ out)
{
    extern __shared__ uint4 sm4[];
    const int tid  = threadIdx.x;
    const int wid  = tid >> 5;
    const int lane = tid & 31;
    const int g    = lane >> 2;
    const int t    = lane & 3;
    const int blockM = blockIdx.x * TILE_M;

    if (wid >= 4) {
        // ------------- producers: warps 4..7 -------------
        const int p = tid - 128;   // 0..127
        float4 xa[8], xb[8];       // one A chunk: 64 floats/thread

        #define PLOAD(c)                                                        \
            {                                                                   \
                _Pragma("unroll")                                               \
                for (int j = 0; j < 8; j++) {                                   \
                    int s_idx = p + 128 * j;          /* 0..1023 */             \
                    int row = s_idx >> 3, q = s_idx & 7;                        \
                    const float* src = X + (size_t)(blockM + row) * KDIM        \
                                         + (size_t)(c) * KC + q * 8;            \
                    xa[j] = reinterpret_cast<const float4*>(src)[0];            \
                    xb[j] = reinterpret_cast<const float4*>(src)[1];            \
                }                                                               \
            }
        #define PSTORE(c)                                                       \
            {                                                                   \
                uint4* aH = sm4 + ((c) & 1) * STAGE_U4;                         \
                _Pragma("unroll")                                               \
                for (int j = 0; j < 8; j++) {                                   \
                    int s_idx = p + 128 * j;                                    \
                    int row = s_idx >> 3, q = s_idx & 7;                        \
                    uint4 H;                                                    \
                    H.x = fpack(xa[j].y, xa[j].x);                              \
                    H.y = fpack(xa[j].w, xa[j].z);                              \
                    H.z = fpack(xb[j].y, xb[j].x);                              \
                    H.w = fpack(xb[j].w, xb[j].z);                              \
                    aH[q * 128 + (row ^ q)] = H;                                \
                }                                                               \
            }
        #define PCOPYB(c)                                                       \
            {                                                                   \
                uint32_t sB = s2u(sm4 + ((c) & 1) * STAGE_U4 + 1024);           \
                const uint4* wb4 = reinterpret_cast<const uint4*>(g_wb);        \
                _Pragma("unroll")                                               \
                for (int j = 0; j < 4; j++) {                                   \
                    int s_idx = p + 128 * j;          /* 0..511 */              \
                    cp16(sB + s_idx * 16, wb4 + (c) * 512 + s_idx);             \
                }                                                               \
                asm volatile("cp.async.commit_group;" ::: "memory");            \
            }
        #define PWAIT() asm volatile("cp.async.wait_group 0;" ::: "memory")

        PLOAD(0);
        PCOPYB(0);
        PSTORE(0);
        PLOAD(1);
        PWAIT();
        __syncthreads();

        for (int c = 0; c < NCH; c++) {
            if (c + 1 < NCH) {
                PCOPYB(c + 1);
                PSTORE(c + 1);
                if (c + 2 < NCH) PLOAD(c + 2);
                PWAIT();
            }
            __syncthreads();
        }
        return;
    }

    // ------------- consumers: warps 0..3, tile m32 x n64 -------------
    float acc[2][8][4];
    #pragma unroll
    for (int mf = 0; mf < 2; mf++)
        #pragma unroll
        for (int nf = 0; nf < 8; nf++)
            #pragma unroll
            for (int u = 0; u < 4; u++) acc[mf][nf][u] = 0.0f;

    const int wbase = wid * 32;
    __syncthreads();   // match producer prologue

    for (int c = 0; c < NCH; c++) {
        const int s = c & 1;
        const uint32_t* aH = reinterpret_cast<const uint32_t*>(sm4 + s * STAGE_U4);
        const uint2*    sB = reinterpret_cast<const uint2*>(sm4 + s * STAGE_U4 + 1024);

        #pragma unroll
        for (int kb = 0; kb < 4; kb++) {
            const int q0 = 2 * kb, q1 = 2 * kb + 1;
            uint32_t ah[2][4];
            #pragma unroll
            for (int mf = 0; mf < 2; mf++) {
                const int R0 = wbase + mf * 16 + g;
                const int i0 = (q0 * 128 + (R0 ^ q0)) * 4 + t;
                const int i2 = (q1 * 128 + (R0 ^ q1)) * 4 + t;
                ah[mf][0] = aH[i0];       ah[mf][1] = aH[i0 + 32];
                ah[mf][2] = aH[i2];       ah[mf][3] = aH[i2 + 32];
            }
            uint2 b[8];
            #pragma unroll
            for (int nf = 0; nf < 8; nf++)
                b[nf] = sB[(kb * 8 + nf) * 32 + lane];
            #pragma unroll
            for (int nf = 0; nf < 8; nf++)
                #pragma unroll
                for (int mf = 0; mf < 2; mf++)
                    mma16(acc[mf][nf], ah[mf], b[nf].x, b[nf].y);
        }
        __syncthreads();
    }

    // ------------- epilogue: logits + approx top-3 + flag -------------
    float* outIdx = out;
    float* outWgt = out + TOKENS * 2;
    float* outLog = out + TOKENS * 4;

    #pragma unroll
    for (int mf = 0; mf < 2; mf++) {
        #pragma unroll
        for (int h = 0; h < 2; h++) {
            const int row = wbase + mf * 16 + h * 8 + g;
            const int tok = blockM + row;

            float v1 = -INFINITY, v2 = -INFINITY, v3 = -INFINITY;
            int   i1 = 0, i2 = 0;
            #pragma unroll
            for (int nf = 0; nf < 8; nf++) {
                #pragma unroll
                for (int u = 0; u < 2; u++) {
                    float v  = acc[mf][nf][2 * h + u];
                    int   id = nf * 8 + 2 * t + u;
                    if (v > v1)      { v3 = v2; v2 = v1; i2 = i1; v1 = v; i1 = id; }
                    else if (v > v2) { v3 = v2; v2 = v;  i2 = id; }
                    else if (v > v3) { v3 = v; }
                }
            }
            merge23(v1, i1, v2, i2, v3, 1);
            merge23(v1, i1, v2, i2, v3, 2);

            float* lr = outLog + (size_t)tok * NEXP;
            #pragma unroll
            for (int nf = 0; nf < 8; nf++) {
                float2 o = make_float2(acc[mf][nf][2 * h], acc[mf][nf][2 * h + 1]);
                *reinterpret_cast<float2*>(lr + nf * 8 + 2 * t) = o;
            }

            if (t == 0) {
                float e2  = expf(v2 - v1);          // v1 >= v2 -> stable
                float inv = 1.0f / (1.0f + e2);
                outIdx[tok * 2]     = (float)i1;
                outIdx[tok * 2 + 1] = (float)i2;
                outWgt[tok * 2]     = inv;
                outWgt[tok * 2 + 1] = e2 * inv;
                g_flag[tok] = ((v1 - v2 < TMARG) || (v2 - v3 < TMARG)) ? 1 : 0;
            }
        }
    }
}

// ---- exact re-rank of flagged tokens (fp32 from gmem) ----
extern "C" __global__ void __launch_bounds__(256)
rerank(const float* __restrict__ X, const float* __restrict__ W,
       float* __restrict__ out)
{
    const int wid  = threadIdx.x >> 5;
    const int lane = threadIdx.x & 31;
    float* outIdx = out;
    float* outWgt = out + TOKENS * 2;
    const float* outLog = out + TOKENS * 4;

    for (int it = 0; it < 4; it++) {
        const int tok = blockIdx.x * 8 + wid + it * 8192;
        if (!g_flag[tok]) continue;

        // approx v2 of the row (values only)
        const float* lr = outLog + (size_t)tok * NEXP;
        float2 lv = reinterpret_cast<const float2*>(lr)[lane];
        float a = fmaxf(lv.x, lv.y), b = fminf(lv.x, lv.y);
        #pragma unroll
        for (int off = 16; off > 0; off >>= 1) {
            float oa = __shfl_xor_sync(0xffffffffu, a, off);
            float ob = __shfl_xor_sync(0xffffffffu, b, off);
            float na = fmaxf(a, oa);
            b = fmaxf(fminf(a, oa), fmaxf(b, ob));
            a = na;
        }
        const float thresh = b - TMARG;

        // preload X row: k = lane + 32*j
        float xr[64];
        const float* xrow = X + (size_t)tok * KDIM;
        #pragma unroll
        for (int j = 0; j < 64; j++) xr[j] = xrow[lane + 32 * j];

        // exact dots for candidates, streaming top-2 (ascending e -> stable ties)
        float e1 = -INFINITY, e2v = -INFINITY;
        int   j1 = 0, j2 = 0;
        for (int e = 0; e < NEXP; e++) {
            float lg = __shfl_sync(0xffffffffu, (lane == (e >> 1))
                                   ? ((e & 1) ? lv.y : lv.x) : 0.0f, e >> 1);
            if (lg >= thresh) {
                const float* wr = W + (size_t)e * KDIM;
                float s = 0.0f;
                #pragma unroll
                for (int j = 0; j < 64; j++) s = fmaf(xr[j], wr[lane + 32 * j], s);
                #pragma unroll
                for (int off = 16; off > 0; off >>= 1)
                    s += __shfl_xor_sync(0xffffffffu, s, off);
                if (s > e1)       { e2v = e1; j2 = j1; e1 = s; j1 = e; }
                else if (s > e2v) { e2v = s;  j2 = e; }
            }
        }
        if (lane == 0) {
            float ex  = expf(e2v - e1);
            float inv = 1.0f / (1.0f + ex);
            outIdx[tok * 2]     = (float)j1;
            outIdx[tok * 2 + 1] = (float)j2;
            outWgt[tok * 2]     = inv;
            outWgt[tok * 2 + 1] = ex * inv;
        }
    }
}

extern "C" void kernel_launch(void* const* d_in, const int* in_sizes, int n_in,
                              void* d_out, int out_size)
{
    const float* X = (const float*)d_in[0];   // [32768, 2048] fp32
    const float* W = (const float*)d_in[1];   // [64, 2048] fp32
    float* out = (float*)d_out;

    prep_w<<<128, 256>>>(W);

    cudaFuncSetAttribute(router_f16,
                         cudaFuncAttributeMaxDynamicSharedMemorySize, SMEM_BYTES);
    router_f16<<<TOKENS / TILE_M, TPB, SMEM_BYTES>>>(X, out);

    rerank<<<1024, 256>>>(X, (const float*)d_in[1], out);
}